// round 15
// baseline (speedup 1.0000x reference)
#include <cuda_runtime.h>
#include <cuda_bf16.h>
#include <cstdint>
#include <cstddef>

#define B_  8
#define C_  512
#define NPIX_ 4096
#define IN_ 32

#define PITCH   24
#define PIXB    48
#define TILE_E2 9504
#define TILE_B2 19008
#define WROWB   48

#define DSA_TILE 31680
#define DSW_CHB  13824
#define SM_DS8   (2 * DSA_TILE + 2 * DSW_CHB)

// ---------------- scratch ----------------
__device__ float g_S[B_ * C_ * 9];
__device__ float g_pooled2[2 * 512];                     // split-K pooled halves
__device__ __nv_bfloat16 g_fbf1[B_ * 9216];
__device__ __nv_bfloat16 g_fbf2[B_ * 9216];
__device__ __nv_bfloat16 g_c1[B_ * IN_ * NPIX_];
__device__ __nv_bfloat16 g_c2[B_ * IN_ * NPIX_];
__device__ __nv_bfloat16 g_part[4 * B_ * IN_ * NPIX_];
__device__ __nv_bfloat16 g_wt_ds[147456];
__device__ __nv_bfloat16 g_wt_up[147456];

// ---------------- helpers ----------------
__device__ __forceinline__ void mma16816(float* c, const uint32_t* a, const uint32_t* b)
{
    asm volatile(
        "mma.sync.aligned.m16n8k16.row.col.f32.bf16.bf16.f32 "
        "{%0,%1,%2,%3}, {%4,%5,%6,%7}, {%8,%9}, {%0,%1,%2,%3};\n"
        : "+f"(c[0]), "+f"(c[1]), "+f"(c[2]), "+f"(c[3])
        : "r"(a[0]), "r"(a[1]), "r"(a[2]), "r"(a[3]), "r"(b[0]), "r"(b[1]));
}
__device__ __forceinline__ void ldsm_x4(uint32_t* r, uint32_t a)
{
    asm volatile("ldmatrix.sync.aligned.m8n8.x4.shared.b16 {%0,%1,%2,%3}, [%4];"
                 : "=r"(r[0]), "=r"(r[1]), "=r"(r[2]), "=r"(r[3]) : "r"(a));
}
__device__ __forceinline__ uint32_t smem_u32(const void* p)
{
    return (uint32_t)__cvta_generic_to_shared(p);
}
__device__ __forceinline__ uint32_t pack_bf2(float a, float b)
{
    __nv_bfloat162 h = __float22bfloat162_rn(make_float2(a, b));
    return *reinterpret_cast<uint32_t*>(&h);
}
__device__ __forceinline__ void cpa16(uint32_t dst, const void* src)
{
    asm volatile("cp.async.cg.shared.global [%0], [%1], 16;" :: "r"(dst), "l"(src));
}
__device__ __forceinline__ void cpa_commit() { asm volatile("cp.async.commit_group;"); }
__device__ __forceinline__ void cpa_wait0()  { asm volatile("cp.async.wait_group 0;" ::: "memory"); }

// ============================================================================
__device__ __forceinline__ void wtrans_body(int idx, const float* __restrict__ w,
                                            __nv_bfloat16* __restrict__ o, int cin, int cout)
{
    int i16 = idx & 15;
    int oc = (idx >> 4) % cout;
    int rest = idx / (16 * cout);
    int nch = cin >> 4;
    int chunk = rest % nch, tap = rest / nch;
    int ic = chunk * 16 + i16;
    o[idx] = __float2bfloat16_rn(w[((size_t)oc * cin + ic) * 9 + tap]);
}

__global__ void wtrans_ds_kernel(const float* __restrict__ ds_w, __nv_bfloat16* __restrict__ wt_ds)
{
    int idx = blockIdx.x * 256 + threadIdx.x;
    wtrans_body(idx, ds_w, wt_ds, C_, IN_);
}

// ============================================================================
// ds conv body (r14-proven)
// ============================================================================
__device__ void ds_body(char* sm8, int b, int s, int ty, int t,
                        const float* __restrict__ x, const __nv_bfloat16* __restrict__ wt,
                        __nv_bfloat16* __restrict__ ypart)
{
    char* s_a = sm8;
    char* s_w = sm8 + 2 * DSA_TILE;
    const int wid = t >> 5, lane = t & 31;
    const int chunk0 = s * 8;
    const int nch = 8;

    for (int e = t; e < 80; e += 256) {
        int buf = e >= 40; int r = e - buf * 40;
        int y_ = r >> 2; int q = r & 3;
        int col = (q & 1) ? 65 : 0; int h = q >> 1;
        *reinterpret_cast<uint4*>(s_a + buf * DSA_TILE + (y_ * 66 + col) * 48 + h * 16) =
            make_uint4(0u, 0u, 0u, 0u);
    }

    uint32_t gofs[5], sofs[5];
    bool pr[5];
    #pragma unroll
    for (int k = 0; k < 5; k++) {
        int idx = t + k * 256;
        int h = idx >= 640;
        int px = idx - h * 640;
        int y_ = px >> 6, x_ = px & 63;
        int gy = ty + y_ - 1;
        pr[k] = ((unsigned)gy < 64u);
        gofs[k] = (h * 8) * NPIX_ + (pr[k] ? gy : 0) * 64 + x_;
        sofs[k] = (y_ * 66 + 1 + x_) * 48 + h * 16;
    }
    const float* xb = x + (size_t)b * C_ * NPIX_;
    const char* wg = reinterpret_cast<const char*>(wt);
    const uint32_t smw = smem_u32(s_w);

    const int wtap0 = t / 64, wr = t & 63;
    const int woc = wr >> 1, whalf = wr & 1;

    auto stageW = [&](int c, int bf) {
        #pragma unroll
        for (int k = 0; k < 3; k++) {
            int u = t + k * 256;
            if (u < 576) {
                int tap = wtap0 + k * 4;
                const char* src = wg + ((size_t)(tap * 32 + c) * 32 + woc) * 32 + whalf * 16;
                cpa16(smw + bf * DSW_CHB + tap * 1536 + woc * 48 + whalf * 16, src);
            }
        }
        cpa_commit();
    };

    const int nb = wid * 64;
    uint32_t addrB[4];
    #pragma unroll
    for (int j = 0; j < 4; j++) {
        int n = nb + j * 16 + ((lane >> 4) & 1) * 8 + (lane & 7);
        addrB[j] = smem_u32(s_a) + ((n >> 6) * 66 + (n & 63)) * 48 + ((lane >> 3) & 1) * 16;
    }
    const int ocrow = (lane & 7) + ((lane >> 3) & 1) * 8;
    const int khalf = (lane >> 4) & 1;
    uint32_t addrA[2];
    #pragma unroll
    for (int mf = 0; mf < 2; mf++)
        addrA[mf] = smw + (mf * 16 + ocrow) * WROWB + khalf * 16;

    float acc[2][8][4];
    #pragma unroll
    for (int mf = 0; mf < 2; mf++)
        #pragma unroll
        for (int f = 0; f < 8; f++)
            #pragma unroll
            for (int q = 0; q < 4; q++) acc[mf][f][q] = 0.f;

    auto loadA = [&](int c, int k) -> uint4 {
        uint4 pk = make_uint4(0u, 0u, 0u, 0u);
        if (pr[k]) {
            const float* g = xb + (size_t)c * 16 * NPIX_ + gofs[k];
            pk.x = pack_bf2(g[0], g[NPIX_]);
            pk.y = pack_bf2(g[2 * NPIX_], g[3 * NPIX_]);
            pk.z = pack_bf2(g[4 * NPIX_], g[5 * NPIX_]);
            pk.w = pack_bf2(g[6 * NPIX_], g[7 * NPIX_]);
        }
        return pk;
    };

    stageW(chunk0, 0);
    #pragma unroll
    for (int k = 0; k < 5; k++) {
        uint4 pk = loadA(chunk0, k);
        *reinterpret_cast<uint4*>(s_a + sofs[k]) = pk;
    }
    cpa_wait0();
    __syncthreads();

    uint4 xv[5];
    for (int i = 0; i < nch; i++) {
        const int bf = i & 1;
        const bool more = (i + 1 < nch);
        if (more) {
            stageW(chunk0 + i + 1, bf ^ 1);
            #pragma unroll
            for (int k = 0; k < 5; k++) xv[k] = loadA(chunk0 + i + 1, k);
        }
        {
            const uint32_t aoff = bf * DSA_TILE;
            const uint32_t woff = bf * DSW_CHB;
            #pragma unroll
            for (int tap = 0; tap < 9; tap++) {
                const int dy = tap / 3, dx = tap - dy * 3;
                const uint32_t shiftB = (dy * 66 + dx) * 48;
                uint32_t a[2][4];
                ldsm_x4(a[0], addrA[0] + woff + tap * 1536);
                ldsm_x4(a[1], addrA[1] + woff + tap * 1536);
                #pragma unroll
                for (int j = 0; j < 4; j++) {
                    uint32_t r[4];
                    ldsm_x4(r, addrB[j] + aoff + shiftB);
                    mma16816(acc[0][2 * j],     a[0], r);
                    mma16816(acc[1][2 * j],     a[1], r);
                    mma16816(acc[0][2 * j + 1], a[0], r + 2);
                    mma16816(acc[1][2 * j + 1], a[1], r + 2);
                }
            }
        }
        if (more) {
            const int nxt = bf ^ 1;
            #pragma unroll
            for (int k = 0; k < 5; k++)
                *reinterpret_cast<uint4*>(s_a + nxt * DSA_TILE + sofs[k]) = xv[k];
            cpa_wait0();
            __syncthreads();
        }
    }

    const int g = lane >> 2, t4 = lane & 3;
    __nv_bfloat16* yb = ypart + ((size_t)(s * B_ + b)) * (IN_ * NPIX_);
    #pragma unroll
    for (int mf = 0; mf < 2; mf++)
        #pragma unroll
        for (int rr = 0; rr < 2; rr++) {
            int oc = mf * 16 + g + rr * 8;
            #pragma unroll
            for (int f = 0; f < 8; f++) {
                int n = nb + f * 8 + t4 * 2;
                size_t off = (size_t)oc * NPIX_ + (size_t)(ty + (n >> 6)) * 64 + (n & 63);
                *reinterpret_cast<uint32_t*>(yb + off) =
                    pack_bf2(acc[mf][f][rr * 2], acc[mf][f][rr * 2 + 1]);
            }
        }
}

// ============================================================================
// Style reduce body (one channel)
// ============================================================================
__device__ void style_body(int i, int b, int t, const float* __restrict__ style,
                           float* __restrict__ S)
{
    const float* p = style + ((size_t)(b * C_ + i)) * NPIX_;
    float T = 0.f, R0 = 0.f, R63 = 0.f, Ca = 0.f, Cb = 0.f;
    #pragma unroll
    for (int k = 0; k < 4; k++) {
        int idx4 = t + k * 256;
        float4 v = reinterpret_cast<const float4*>(p)[idx4];
        int y = idx4 >> 4, xq = idx4 & 15;
        float s = v.x + v.y + v.z + v.w;
        T += s;
        if (y == 0) R0 += s;
        if (y == 63) R63 += s;
        if (xq == 0) Ca += v.x;
        if (xq == 15) Cb += v.w;
    }
    __shared__ float red[5][8];
    float vals[5] = {T, R0, R63, Ca, Cb};
    const int lane = t & 31, wid = t >> 5;
    #pragma unroll
    for (int j = 0; j < 5; j++) {
        float v = vals[j];
        #pragma unroll
        for (int off = 16; off; off >>= 1) v += __shfl_xor_sync(0xffffffffu, v, off);
        if (lane == 0) red[j][wid] = v;
    }
    __syncthreads();
    if (t == 0) {
        float tv[5];
        #pragma unroll
        for (int j = 0; j < 5; j++) {
            float s = 0.f;
            #pragma unroll
            for (int wq = 0; wq < 8; wq++) s += red[j][wq];
            tv[j] = s;
        }
        const float c00 = p[0], c0e = p[63], ce0 = p[63 * 64], cee = p[63 * 64 + 63];
        float* out = S + (size_t)(b * C_ + i) * 9;
        #pragma unroll
        for (int ky = 0; ky < 3; ky++)
            #pragma unroll
            for (int kx = 0; kx < 3; kx++) {
                float s = tv[0];
                if (ky == 0) s -= tv[2];
                if (ky == 2) s -= tv[1];
                if (kx == 0) s -= tv[4];
                if (kx == 2) s -= tv[3];
                if (ky == 0 && kx == 0) s += cee;
                if (ky == 0 && kx == 2) s += ce0;
                if (ky == 2 && kx == 0) s += c0e;
                if (ky == 2 && kx == 2) s += c00;
                out[ky * 3 + kx] = s;
            }
    }
    __syncthreads();
}

// ============================================================================
// MEGA kernel (r14-proven layout)
// ============================================================================
__global__ void __launch_bounds__(256, 2)
mega_kernel(const float* __restrict__ content, const float* __restrict__ style,
            const float* __restrict__ up_w,
            const __nv_bfloat16* __restrict__ wt_ds,
            __nv_bfloat16* __restrict__ wt_up,
            float* __restrict__ S, __nv_bfloat16* __restrict__ ypart)
{
    extern __shared__ __align__(16) char sm8[];
    const int bid = blockIdx.x, t = threadIdx.x;
    if (bid < 256) {
        ds_body(sm8, bid >> 5, (bid >> 3) & 3, (bid & 7) * 8, t, content, wt_ds, ypart);
    } else if (bid < 768) {
        int r = bid - 256;
        int b = r >> 6, g8 = (r & 63) * 8;
        #pragma unroll
        for (int ch = 0; ch < 8; ch++)
            style_body(g8 + ch, b, t, style, S);
    } else {
        wtrans_body((bid - 768) * 256 + t, up_w, wt_up, IN_, C_);
    }
}

// ============================================================================
// Pooled, split-K=2: block = (b,o,half); raw dot halves (no bias/scale yet)
// ============================================================================
__global__ void pooled_kernel(const float* __restrict__ S,
                              const float* __restrict__ cw1,
                              const float* __restrict__ cw2,
                              float* __restrict__ pooled2)
{
    const int bid = blockIdx.x;
    const int half = bid & 1, bo = bid >> 1;
    const int b = bo >> 6, o = bo & 63, oo = o & 31;
    const int t = threadIdx.x;
    const float* cw = ((o < 32) ? cw1 : cw2) + (size_t)oo * 4608 + half * 2304;
    const float* Sb = S + (size_t)b * 4608 + half * 2304;

    float s = 0.f;
    #pragma unroll
    for (int k = 0; k < 9; k++) {
        int idx = t + k * 256;
        s = fmaf(cw[idx], Sb[idx], s);
    }
    __shared__ float red[8];
    const int lane = t & 31, wid = t >> 5;
    #pragma unroll
    for (int off = 16; off; off >>= 1) s += __shfl_xor_sync(0xffffffffu, s, off);
    if (lane == 0) red[wid] = s;
    __syncthreads();
    if (t == 0) {
        float tot = 0.f;
        #pragma unroll
        for (int w = 0; w < 8; w++) tot += red[w];
        pooled2[half * 512 + bo] = tot;
    }
}

// ============================================================================
// filt body: thread computes coeff j for a pair of batches. PRED selects
// predictor half. sp prep: combine pooled halves + scale + bias.
// ============================================================================
__device__ __forceinline__ void filt_body(int task, int t, float* sp,
                                          const float* __restrict__ pooled2,
                                          const float* __restrict__ cb1,
                                          const float* __restrict__ cb2,
                                          const float* __restrict__ fw,
                                          const float* __restrict__ fb,
                                          __nv_bfloat16* __restrict__ fo, int poff)
{
    #pragma unroll
    for (int k = 0; k < 2; k++) {
        int i = t + k * 256;
        int o = i & 63;
        float cb = (o < 32) ? cb1[o] : cb2[o - 32];
        sp[i] = (pooled2[i] + pooled2[512 + i]) * (1.f / 4096.f) + cb;
    }
    __syncthreads();

    int j = task % 9216;
    int bp = task / 9216;          // batch pair 0..3
    float4 w[8];
    const float4* fw4 = reinterpret_cast<const float4*>(fw + (size_t)j * 32);
    #pragma unroll
    for (int q = 0; q < 8; q++) w[q] = fw4[q];
    float fb_ = fb[j];

    int oc = j / 288, r2 = j - oc * 288;
    int ic = r2 / 9, tap = r2 - ic * 9;
    int oidx = ((tap * 2 + (ic >> 4)) * 32 + oc) * 16 + (ic & 15);

    #pragma unroll
    for (int bb = 0; bb < 2; bb++) {
        int b = bp * 2 + bb;
        const float* pp = sp + b * 64 + poff;
        float v = fb_;
        #pragma unroll
        for (int q = 0; q < 8; q++) {
            v = fmaf(w[q].x, pp[q * 4 + 0], v);
            v = fmaf(w[q].y, pp[q * 4 + 1], v);
            v = fmaf(w[q].z, pp[q * 4 + 2], v);
            v = fmaf(w[q].w, pp[q * 4 + 3], v);
        }
        fo[(size_t)b * 9216 + oidx] = __float2bfloat16_rn(v);
    }
}

// filt1: predictor 1, 144 blocks (9216 j x 4 batch pairs)
__global__ void filt1_kernel(const float* __restrict__ pooled2,
                             const float* __restrict__ cb1, const float* __restrict__ cb2,
                             const float* __restrict__ fw1, const float* __restrict__ fb1,
                             __nv_bfloat16* __restrict__ fo1)
{
    __shared__ float sp[512];
    filt_body(blockIdx.x * 256 + threadIdx.x, threadIdx.x, sp,
              pooled2, cb1, cb2, fw1, fb1, fo1, 0);
}

// ============================================================================
// cin=32 conv. COMB: fused ds-partial combine. FILT2: extra blocks (bx>=16)
// compute predictor-2 filters instead of conv work.
// ============================================================================
template <int MT, int NFRAG, int EPI, bool COMB, bool FILT2>
__global__ void __launch_bounds__(256, 2)
conv_s2_kernel(const __nv_bfloat16* __restrict__ x, const __nv_bfloat16* __restrict__ wt,
               const float* __restrict__ bias, const float* __restrict__ resid,
               void* __restrict__ y, int cout, int wstride,
               const float* __restrict__ cbias,
               const float* __restrict__ pooled2,
               const float* __restrict__ cb1, const float* __restrict__ cb2,
               const float* __restrict__ fw2, const float* __restrict__ fb2,
               __nv_bfloat16* __restrict__ fo2)
{
    extern __shared__ __align__(16) char smraw[];

    if (FILT2 && blockIdx.x >= 16) {
        float* sp = reinterpret_cast<float*>(smraw);
        int task = ((int)blockIdx.z * 18 + ((int)blockIdx.x - 16)) * 256 + threadIdx.x;
        filt_body(task, threadIdx.x, sp, pooled2, cb1, cb2, fw2, fb2, fo2, 32);
        return;
    }

    __nv_bfloat16* s_x = reinterpret_cast<__nv_bfloat16*>(smraw);
    __nv_bfloat16* s_a = reinterpret_cast<__nv_bfloat16*>(smraw + 2 * TILE_B2);

    const int b = blockIdx.z;
    const int ocb = blockIdx.y * MT;
    const int ty = blockIdx.x * 4;
    const int t = threadIdx.x;
    const int wid = t >> 5, lane = t & 31;

    const int wm = (MT == 32) ? 0 : (wid >> 2) * 32;
    const int nb = (MT == 32) ? wid * 32 : (wid & 3) * 64;

    for (int e = t; e < 384; e += 256) {
        int buf = e >= 192; int r = e - buf * 192;
        int y_ = r >> 5; int ci = r & 31;
        int col = (ci >= 16) ? 65 : 0;
        s_x[buf * TILE_E2 + (y_ * 66 + col) * PITCH + (ci & 15)] = __float2bfloat16_rn(0.f);
    }

    const __nv_bfloat16* xb = x + (size_t)b * IN_ * NPIX_;
    const int SOFF = B_ * IN_ * NPIX_;
    #pragma unroll
    for (int k = 0; k < 6; k++) {
        int idx = t + k * 256;
        int q = idx / 384;
        int px = idx - q * 384;
        int chunkid = q >> 1, h = q & 1;
        int y_ = px >> 6, x_ = px & 63;
        int gy = ty + y_ - 1;
        uint4 pk = make_uint4(0u, 0u, 0u, 0u);
        if ((unsigned)gy < 64u) {
            const __nv_bfloat16* g = xb + (size_t)(chunkid * 16 + h * 8) * NPIX_ + gy * 64 + x_;
            if (COMB) {
                unsigned short e[8];
                #pragma unroll
                for (int j = 0; j < 8; j++) {
                    const __nv_bfloat16* gj = g + (size_t)j * NPIX_;
                    float v = __bfloat162float(gj[0])
                            + __bfloat162float(gj[SOFF])
                            + __bfloat162float(gj[2 * SOFF])
                            + __bfloat162float(gj[3 * SOFF])
                            + cbias[chunkid * 16 + h * 8 + j];
                    __nv_bfloat16 hb = __float2bfloat16_rn(v);
                    e[j] = *reinterpret_cast<unsigned short*>(&hb);
                }
                pk.x = (uint32_t)e[0] | ((uint32_t)e[1] << 16);
                pk.y = (uint32_t)e[2] | ((uint32_t)e[3] << 16);
                pk.z = (uint32_t)e[4] | ((uint32_t)e[5] << 16);
                pk.w = (uint32_t)e[6] | ((uint32_t)e[7] << 16);
            } else {
                const unsigned short* gs = reinterpret_cast<const unsigned short*>(g);
                pk.x = (uint32_t)gs[0] | ((uint32_t)gs[NPIX_] << 16);
                pk.y = (uint32_t)gs[2 * NPIX_] | ((uint32_t)gs[3 * NPIX_] << 16);
                pk.z = (uint32_t)gs[4 * NPIX_] | ((uint32_t)gs[5 * NPIX_] << 16);
                pk.w = (uint32_t)gs[6 * NPIX_] | ((uint32_t)gs[7 * NPIX_] << 16);
            }
        }
        *reinterpret_cast<uint4*>(s_x + chunkid * TILE_E2 + (y_ * 66 + 1 + x_) * PITCH + h * 8) = pk;
    }

    {
        const uint4* wsrc = reinterpret_cast<const uint4*>(wt + (size_t)b * wstride);
        uint4* s_a4 = reinterpret_cast<uint4*>(s_a);
        const int TOT4 = 18 * MT * 2;
        for (int u = t; u < TOT4; u += 256) {
            int slice = u / (MT * 2), j = u - slice * (MT * 2);
            int oc = j >> 1, half = j & 1;
            s_a4[slice * (MT * 3) + oc * 3 + half] =
                wsrc[(size_t)slice * (cout * 2) + ocb * 2 + j];
        }
    }
    __syncthreads();

    uint32_t addrB[NFRAG / 2];
    #pragma unroll
    for (int j = 0; j < NFRAG / 2; j++) {
        int n = nb + j * 16 + ((lane >> 4) & 1) * 8 + (lane & 7);
        addrB[j] = smem_u32(s_x) + ((n >> 6) * 66 + (n & 63)) * PIXB + ((lane >> 3) & 1) * 16;
    }
    const int ocrow = (lane & 7) + ((lane >> 3) & 1) * 8;
    const int khalf = (lane >> 4) & 1;
    uint32_t addrA[2];
    #pragma unroll
    for (int mf = 0; mf < 2; mf++)
        addrA[mf] = smem_u32(s_a) + (wm + mf * 16 + ocrow) * WROWB + khalf * 16;

    float acc[2][NFRAG][4];
    #pragma unroll
    for (int mf = 0; mf < 2; mf++)
        #pragma unroll
        for (int f = 0; f < NFRAG; f++)
            #pragma unroll
            for (int q = 0; q < 4; q++) acc[mf][f][q] = 0.f;

    #pragma unroll
    for (int cc = 0; cc < 2; cc++) {
        const uint32_t xoff = cc * TILE_B2;
        #pragma unroll
        for (int tap = 0; tap < 9; tap++) {
            const int dy = tap / 3, dx = tap - dy * 3;
            const uint32_t shiftB = (dy * 66 + dx) * PIXB;
            const uint32_t woff = (tap * 2 + cc) * (MT * WROWB);
            uint32_t a[2][4];
            ldsm_x4(a[0], addrA[0] + woff);
            ldsm_x4(a[1], addrA[1] + woff);
            #pragma unroll
            for (int j = 0; j < NFRAG / 2; j++) {
                uint32_t r[4];
                ldsm_x4(r, addrB[j] + xoff + shiftB);
                mma16816(acc[0][2 * j],     a[0], r);
                mma16816(acc[1][2 * j],     a[1], r);
                mma16816(acc[0][2 * j + 1], a[0], r + 2);
                mma16816(acc[1][2 * j + 1], a[1], r + 2);
            }
        }
    }

    const int g = lane >> 2, t4 = lane & 3;
    #pragma unroll
    for (int mf = 0; mf < 2; mf++) {
        int oc0 = ocb + wm + mf * 16 + g;
        #pragma unroll
        for (int rr = 0; rr < 2; rr++) {
            int oc = oc0 + rr * 8;
            float bv = (EPI == 3) ? bias[oc] : 0.f;
            #pragma unroll
            for (int f = 0; f < NFRAG; f++) {
                int n = nb + f * 8 + t4 * 2;
                size_t off = (size_t)oc * NPIX_ + ty * 64 + n;
                float u0 = acc[mf][f][rr * 2 + 0];
                float u1 = acc[mf][f][rr * 2 + 1];
                if (EPI == 2) {
                    u0 = (u0 >= 0.f) ? u0 : 0.2f * u0;
                    u1 = (u1 >= 0.f) ? u1 : 0.2f * u1;
                }
                if (EPI == 3) {
                    float* yb = (float*)y + (size_t)b * cout * NPIX_;
                    float2 rv = *reinterpret_cast<const float2*>(
                        resid + (size_t)b * cout * NPIX_ + off);
                    *reinterpret_cast<float2*>(yb + off) =
                        make_float2(u0 + bv + rv.x, u1 + bv + rv.y);
                } else {
                    __nv_bfloat16* yb = (__nv_bfloat16*)y + (size_t)b * cout * NPIX_;
                    __nv_bfloat162 h;
                    h.x = __float2bfloat16_rn(u0);
                    h.y = __float2bfloat16_rn(u1);
                    *reinterpret_cast<__nv_bfloat162*>(yb + off) = h;
                }
            }
        }
    }
}

// ============================================================================
extern "C" void kernel_launch(void* const* d_in, const int* in_sizes, int n_in,
                              void* d_out, int out_size)
{
    const float* content = (const float*)d_in[0];
    const float* style   = (const float*)d_in[1];
    const float* ds_w    = (const float*)d_in[2];
    const float* ds_b    = (const float*)d_in[3];
    const float* up_w    = (const float*)d_in[4];
    const float* up_b    = (const float*)d_in[5];
    const float* f1_cw   = (const float*)d_in[6];
    const float* f1_cb   = (const float*)d_in[7];
    const float* f1_fw   = (const float*)d_in[8];
    const float* f1_fb   = (const float*)d_in[9];
    const float* f2_cw   = (const float*)d_in[10];
    const float* f2_cb   = (const float*)d_in[11];
    const float* f2_fw   = (const float*)d_in[12];
    const float* f2_fb   = (const float*)d_in[13];
    float* out = (float*)d_out;

    float *pS, *pPool2;
    __nv_bfloat16 *pF1, *pF2, *pC1, *pC2, *pWds, *pWup, *pPart;
    cudaGetSymbolAddress((void**)&pS,  g_S);
    cudaGetSymbolAddress((void**)&pPool2, g_pooled2);
    cudaGetSymbolAddress((void**)&pF1, g_fbf1);
    cudaGetSymbolAddress((void**)&pF2, g_fbf2);
    cudaGetSymbolAddress((void**)&pC1, g_c1);
    cudaGetSymbolAddress((void**)&pC2, g_c2);
    cudaGetSymbolAddress((void**)&pPart, g_part);
    cudaGetSymbolAddress((void**)&pWds, g_wt_ds);
    cudaGetSymbolAddress((void**)&pWup, g_wt_up);

    const int SM_DYN = 2 * TILE_B2 + 18 * 32 * WROWB;
    const int SM_UP  = 2 * TILE_B2 + 18 * 64 * WROWB;

    cudaFuncSetAttribute(mega_kernel, cudaFuncAttributeMaxDynamicSharedMemorySize, SM_DS8);
    cudaFuncSetAttribute(conv_s2_kernel<32, 4, 2, true, true>,
                         cudaFuncAttributeMaxDynamicSharedMemorySize, SM_DYN);
    cudaFuncSetAttribute(conv_s2_kernel<32, 4, 1, false, false>,
                         cudaFuncAttributeMaxDynamicSharedMemorySize, SM_DYN);
    cudaFuncSetAttribute(conv_s2_kernel<64, 8, 3, false, false>,
                         cudaFuncAttributeMaxDynamicSharedMemorySize, SM_UP);

    // 1) ds weight transpose
    wtrans_ds_kernel<<<576, 256>>>(ds_w, pWds);

    // 2) MEGA: ds conv + style reduce + up wtrans
    mega_kernel<<<1344, 256, SM_DS8>>>(content, style, up_w, pWds, pWup, pS, pPart);

    // 3) pooled (split-K=2, 1024 blocks)
    pooled_kernel<<<1024, 256>>>(pS, f1_cw, f2_cw, pPool2);

    // 4) filters, predictor 1 only (144 blocks)
    filt1_kernel<<<144, 256>>>(pPool2, f1_cb, f2_cb, f1_fw, f1_fb, pF1);

    // 5) dyn conv 1 (+fused combine) with predictor-2 filter blocks backfilled
    conv_s2_kernel<32, 4, 2, true, true><<<dim3(34, 1, B_), 256, SM_DYN>>>(
        pPart, pF1, nullptr, nullptr, pC1, IN_, 9216, ds_b,
        pPool2, f1_cb, f2_cb, f2_fw, f2_fb, pF2);

    // 6) dyn conv 2
    conv_s2_kernel<32, 4, 1, false, false><<<dim3(16, 1, B_), 256, SM_DYN>>>(
        pC1, pF2, nullptr, nullptr, pC2, IN_, 9216, nullptr,
        nullptr, nullptr, nullptr, nullptr, nullptr, nullptr);

    // 7) up conv + bias + residual
    conv_s2_kernel<64, 8, 3, false, false><<<dim3(16, 8, B_), 256, SM_UP>>>(
        pC2, pWup, up_b, content, out, C_, 0, nullptr,
        nullptr, nullptr, nullptr, nullptr, nullptr, nullptr);
}